// round 2
// baseline (speedup 1.0000x reference)
#include <cuda_runtime.h>
#include <cuda_bf16.h>
#include <math.h>

// ---------------- problem constants ----------------
#define Bz   2048
#define Tz   71
#define Dz   1024
#define Hz   8
#define DHz  128
#define Lz   12
#define NTOK (Bz*Tz)            // 145408
#define MTILES (NTOK/128)       // 1136

// ---------------- device scratch (allocation-free rule: __device__ globals) ----------------
__device__ float g_x [NTOK*Dz];   // activations (B,T,D)
__device__ float g_q [NTOK*Dz];
__device__ float g_k [NTOK*Dz];
__device__ float g_v [NTOK*Dz];
__device__ float g_y1[NTOK*Dz];   // ff1 output
__device__ float g_t [Bz*2*Dz];   // head: gathered+LN tokens (B, 2048)
__device__ float g_h1[Bz*2*Dz];   // head: hidden
__device__ float g_w1t[2*Dz*2*Dz]; // W1 transposed (2048x2048)

__device__ __forceinline__ float lrelu(float x) { return x > 0.f ? x : 0.2f * x; }

// ---------------- block reduction (sum of two values, 256 threads) ----------------
__device__ __forceinline__ void blockReduce2(float& s1, float& s2) {
    __shared__ float buf[32];
    int lane = threadIdx.x & 31, warp = threadIdx.x >> 5;
#pragma unroll
    for (int o = 16; o; o >>= 1) {
        s1 += __shfl_xor_sync(0xffffffffu, s1, o);
        s2 += __shfl_xor_sync(0xffffffffu, s2, o);
    }
    if (lane == 0) { buf[warp] = s1; buf[16 + warp] = s2; }
    __syncthreads();
    float t1 = 0.f, t2 = 0.f;
#pragma unroll
    for (int w = 0; w < 8; ++w) { t1 += buf[w]; t2 += buf[16 + w]; }
    s1 = t1; s2 = t2;
}

// ---------------- embedding + layernorm ----------------
__global__ void __launch_bounds__(256) embed_kernel(
    const int* __restrict__ fen, const int* __restrict__ move,
    const float* __restrict__ rank_emb, const float* __restrict__ file_emb,
    const float* __restrict__ fen_emb, const float* __restrict__ move_emb,
    const float* __restrict__ lng, const float* __restrict__ lnb,
    const float* __restrict__ abs_emb)
{
    int token = blockIdx.x;
    int b = token / Tz, t = token - b * Tz;
    int tid = threadIdx.x;
    float vals[4];

    if (t < 64) {
        int i1 = fen[b * 133 + t];
        int i2 = fen[b * 133 + 64 + t];
        int r = t >> 3, f = t & 7;
#pragma unroll
        for (int c = 0; c < 4; ++c) {
            int d = tid + c * 256;
            vals[c] = 0.5f * (fen_emb[i1 * Dz + d] + fen_emb[i2 * Dz + d]
                              + rank_emb[r * Dz + d] + file_emb[f * Dz + d])
                      + abs_emb[t * Dz + d];
        }
    } else if (t < 69) {
        int i1 = fen[b * 133 + 128 + (t - 64)];
#pragma unroll
        for (int c = 0; c < 4; ++c) {
            int d = tid + c * 256;
            vals[c] = fen_emb[i1 * Dz + d] + abs_emb[t * Dz + d];
        }
    } else {
        int i = t - 69;
        int m = move[b * 2 + i];
        int r = m >> 3, f = m & 7;
#pragma unroll
        for (int c = 0; c < 4; ++c) {
            int d = tid + c * 256;
            vals[c] = (rank_emb[r * Dz + d] + file_emb[f * Dz + d] + move_emb[i * Dz + d]) * 0.58f
                      + abs_emb[t * Dz + d];
        }
    }

    float s1 = 0.f, s2 = 0.f;
#pragma unroll
    for (int c = 0; c < 4; ++c) { s1 += vals[c]; s2 += vals[c] * vals[c]; }
    blockReduce2(s1, s2);
    float mean = s1 * (1.f / 1024.f);
    float var  = s2 * (1.f / 1024.f) - mean * mean;
    float inv  = rsqrtf(var + 1e-5f);

    float* xp = g_x + (size_t)token * Dz;
#pragma unroll
    for (int c = 0; c < 4; ++c) {
        int d = tid + c * 256;
        xp[d] = (vals[c] - mean) * inv * lng[d] + lnb[d];
    }
}

// ---------------- 128x128x8 fp32 GEMM core (256 threads, 8x8 microtile) ----------------
// A: row-major, tile origin pre-offset (128 rows, K cols, leading dim lda)
// B: row-major K x 128, leading dim ldb, tile origin pre-offset
__device__ __forceinline__ void sgemm_128(const float* __restrict__ A, int lda,
                                          const float* __restrict__ Bm, int ldb,
                                          int K, float (&acc)[8][8])
{
    __shared__ float As[8 * 132];
    __shared__ float Bs[8 * 128];
    const int tid  = threadIdx.x;
    const int arow = tid >> 1;
    const int aseg = (tid & 1) << 2;
    const int brow = tid >> 5;
    const int bcol = (tid & 31) << 2;
    const int tx = tid & 15, ty = tid >> 4;

    for (int kk = 0; kk < K; kk += 8) {
        float4 av = *reinterpret_cast<const float4*>(A + (size_t)arow * lda + kk + aseg);
        As[(aseg + 0) * 132 + arow] = av.x;
        As[(aseg + 1) * 132 + arow] = av.y;
        As[(aseg + 2) * 132 + arow] = av.z;
        As[(aseg + 3) * 132 + arow] = av.w;
        *reinterpret_cast<float4*>(&Bs[brow * 128 + bcol]) =
            *reinterpret_cast<const float4*>(Bm + (size_t)(kk + brow) * ldb + bcol);
        __syncthreads();
#pragma unroll
        for (int p = 0; p < 8; ++p) {
            float4 a0 = *reinterpret_cast<const float4*>(&As[p * 132 + ty * 8]);
            float4 a1 = *reinterpret_cast<const float4*>(&As[p * 132 + ty * 8 + 4]);
            float4 b0 = *reinterpret_cast<const float4*>(&Bs[p * 128 + tx * 8]);
            float4 b1 = *reinterpret_cast<const float4*>(&Bs[p * 128 + tx * 8 + 4]);
            float a[8] = {a0.x, a0.y, a0.z, a0.w, a1.x, a1.y, a1.z, a1.w};
            float bb[8] = {b0.x, b0.y, b0.z, b0.w, b1.x, b1.y, b1.z, b1.w};
#pragma unroll
            for (int i = 0; i < 8; ++i)
#pragma unroll
                for (int j = 0; j < 8; ++j)
                    acc[i][j] = fmaf(a[i], bb[j], acc[i][j]);
        }
        __syncthreads();
    }
}

// ---------------- QKV projection: per (s,h): [M,128] = x[:,h*128:+128] @ W[128,128] ----------------
__global__ void __launch_bounds__(256) qkv_kernel(const float* __restrict__ qkvw)
{
    int m0 = blockIdx.x * 128;
    int sh = blockIdx.y;                 // 0..23 = s*8+h
    int s = sh >> 3, h = sh & 7;
    const float* A  = g_x + (size_t)m0 * Dz + h * DHz;
    const float* Bm = qkvw + (size_t)sh * (DHz * DHz);
    float acc[8][8] = {};
    sgemm_128(A, Dz, Bm, DHz, DHz, acc);

    float* out = (s == 0) ? g_q : (s == 1) ? g_k : g_v;
    int tx = threadIdx.x & 15, ty = threadIdx.x >> 4;
#pragma unroll
    for (int i = 0; i < 8; ++i) {
        size_t row = (size_t)m0 + ty * 8 + i;
        float* dst = out + row * Dz + h * DHz + tx * 8;
        float4 o0 = make_float4(acc[i][0], acc[i][1], acc[i][2], acc[i][3]);
        float4 o1 = make_float4(acc[i][4], acc[i][5], acc[i][6], acc[i][7]);
        *reinterpret_cast<float4*>(dst)     = o0;
        *reinterpret_cast<float4*>(dst + 4) = o1;
    }
}

// ---------------- attention: one CTA per (b,h); softmax(qk^T/sqrt(dh)) @ v, residual into x ----------------
__global__ void __launch_bounds__(256) attn_kernel()
{
    int b = blockIdx.x, h = blockIdx.y;
    int tid = threadIdx.x;
    extern __shared__ float sm[];
    float* qs = sm;                    // 71*128
    float* ks = qs + Tz * 128;         // 71*129 (padded: conflict-free column dots)
    float* vs = ks + Tz * 129;         // 71*128
    float* ps = vs + Tz * 128;         // 71*72

    const float* qb = g_q + ((size_t)b * Tz) * Dz + h * DHz;
    const float* kb = g_k + ((size_t)b * Tz) * Dz + h * DHz;
    const float* vb = g_v + ((size_t)b * Tz) * Dz + h * DHz;

    for (int i = tid; i < Tz * 128; i += 256) {
        int t = i >> 7, d = i & 127;
        qs[t * 128 + d] = qb[(size_t)t * Dz + d];
        ks[t * 129 + d] = kb[(size_t)t * Dz + d];
        vs[t * 128 + d] = vb[(size_t)t * Dz + d];
    }
    __syncthreads();

    const float inv_scale = 0.08838834764831845f;  // 1/sqrt(128)
    for (int idx = tid; idx < Tz * Tz; idx += 256) {
        int i = idx / Tz, j = idx - i * Tz;
        float s = 0.f;
#pragma unroll 8
        for (int dd = 0; dd < 128; ++dd)
            s = fmaf(qs[i * 128 + dd], ks[j * 129 + dd], s);
        ps[i * 72 + j] = s * inv_scale;
    }
    __syncthreads();

    int warp = tid >> 5, lane = tid & 31;
    for (int r = warp; r < Tz; r += 8) {
        float m = -1e30f;
        for (int j = lane; j < Tz; j += 32) m = fmaxf(m, ps[r * 72 + j]);
#pragma unroll
        for (int o = 16; o; o >>= 1) m = fmaxf(m, __shfl_xor_sync(0xffffffffu, m, o));
        float ssum = 0.f;
        for (int j = lane; j < Tz; j += 32) {
            float e = expf(ps[r * 72 + j] - m);
            ps[r * 72 + j] = e;
            ssum += e;
        }
#pragma unroll
        for (int o = 16; o; o >>= 1) ssum += __shfl_xor_sync(0xffffffffu, ssum, o);
        float inv = 1.f / ssum;
        for (int j = lane; j < Tz; j += 32) ps[r * 72 + j] *= inv;
    }
    __syncthreads();

    float* xb = g_x + ((size_t)b * Tz) * Dz + h * DHz;
    for (int idx = tid; idx < Tz * 128; idx += 256) {
        int i = idx >> 7, d = idx & 127;
        float a = 0.f;
#pragma unroll 8
        for (int j = 0; j < Tz; ++j)
            a = fmaf(ps[i * 72 + j], vs[j * 128 + d], a);
        xb[(size_t)i * Dz + d] += a;   // residual
    }
}

// ---------------- FF1: [M,1024] x per-head [1024,128] -> leaky -> y1 ----------------
__global__ void __launch_bounds__(256) ff1_kernel(const float* __restrict__ ff1w)
{
    int m0 = blockIdx.x * 128;
    int h = blockIdx.y;
    const float* A  = g_x + (size_t)m0 * Dz;
    const float* Bm = ff1w + (size_t)h * (Dz * DHz);
    float acc[8][8] = {};
    sgemm_128(A, Dz, Bm, DHz, Dz, acc);

    int tx = threadIdx.x & 15, ty = threadIdx.x >> 4;
#pragma unroll
    for (int i = 0; i < 8; ++i) {
        size_t row = (size_t)m0 + ty * 8 + i;
        float* dst = g_y1 + row * Dz + h * DHz + tx * 8;
        float4 o0 = make_float4(lrelu(acc[i][0]), lrelu(acc[i][1]), lrelu(acc[i][2]), lrelu(acc[i][3]));
        float4 o1 = make_float4(lrelu(acc[i][4]), lrelu(acc[i][5]), lrelu(acc[i][6]), lrelu(acc[i][7]));
        *reinterpret_cast<float4*>(dst)     = o0;
        *reinterpret_cast<float4*>(dst + 4) = o1;
    }
}

// ---------------- FF2: per-head [M,128] x [128,128] -> leaky -> residual into x ----------------
__global__ void __launch_bounds__(256) ff2_kernel(const float* __restrict__ ff2w)
{
    int m0 = blockIdx.x * 128;
    int h = blockIdx.y;
    const float* A  = g_y1 + (size_t)m0 * Dz + h * DHz;
    const float* Bm = ff2w + (size_t)h * (DHz * DHz);
    float acc[8][8] = {};
    sgemm_128(A, Dz, Bm, DHz, DHz, acc);

    int tx = threadIdx.x & 15, ty = threadIdx.x >> 4;
#pragma unroll
    for (int i = 0; i < 8; ++i) {
        size_t row = (size_t)m0 + ty * 8 + i;
        float* dst = g_x + row * Dz + h * DHz + tx * 8;
        float4 x0 = *reinterpret_cast<const float4*>(dst);
        float4 x1 = *reinterpret_cast<const float4*>(dst + 4);
        x0.x += lrelu(acc[i][0]); x0.y += lrelu(acc[i][1]);
        x0.z += lrelu(acc[i][2]); x0.w += lrelu(acc[i][3]);
        x1.x += lrelu(acc[i][4]); x1.y += lrelu(acc[i][5]);
        x1.z += lrelu(acc[i][6]); x1.w += lrelu(acc[i][7]);
        *reinterpret_cast<float4*>(dst)     = x0;
        *reinterpret_cast<float4*>(dst + 4) = x1;
    }
}

// ---------------- head: W1 transpose ----------------
__global__ void transpose2048(const float* __restrict__ W)
{
    __shared__ float tile[32][33];
    int x0 = blockIdx.x * 32, y0 = blockIdx.y * 32;
    for (int i = threadIdx.y; i < 32; i += 8)
        tile[i][threadIdx.x] = W[(size_t)(y0 + i) * 2048 + x0 + threadIdx.x];
    __syncthreads();
    for (int i = threadIdx.y; i < 32; i += 8)
        g_w1t[(size_t)(x0 + i) * 2048 + y0 + threadIdx.x] = tile[threadIdx.x][i];
}

// ---------------- head: gather tokens 69,70 + layernorm over 2048 ----------------
__global__ void __launch_bounds__(256) gather_ln_kernel(const float* __restrict__ g,
                                                        const float* __restrict__ bb)
{
    int b = blockIdx.x, tid = threadIdx.x;
    const float* x69 = g_x + ((size_t)b * Tz + 69) * Dz;  // tokens 69,70 are contiguous
    float vals[8];
#pragma unroll
    for (int c = 0; c < 8; ++c) vals[c] = x69[tid + c * 256];
    float s1 = 0.f, s2 = 0.f;
#pragma unroll
    for (int c = 0; c < 8; ++c) { s1 += vals[c]; s2 += vals[c] * vals[c]; }
    blockReduce2(s1, s2);
    float mean = s1 * (1.f / 2048.f);
    float var  = s2 * (1.f / 2048.f) - mean * mean;
    float inv  = rsqrtf(var + 1e-5f);
    float* tp = g_t + (size_t)b * 2048;
#pragma unroll
    for (int c = 0; c < 8; ++c) {
        int k = tid + c * 256;
        tp[k] = (vals[c] - mean) * inv * g[k] + bb[k];
    }
}

// ---------------- head: h1 = leaky(t @ W1^T + b1) ----------------
__global__ void __launch_bounds__(256) head_gemm_kernel(const float* __restrict__ b1)
{
    int m0 = blockIdx.x * 128;
    int n0 = blockIdx.y * 128;
    float acc[8][8] = {};
    sgemm_128(g_t + (size_t)m0 * 2048, 2048, g_w1t + n0, 2048, 2048, acc);

    int tx = threadIdx.x & 15, ty = threadIdx.x >> 4;
#pragma unroll
    for (int i = 0; i < 8; ++i) {
        size_t row = (size_t)m0 + ty * 8 + i;
        float* dst = g_h1 + row * 2048 + n0 + tx * 8;
#pragma unroll
        for (int j = 0; j < 8; ++j)
            dst[j] = lrelu(acc[i][j] + b1[n0 + tx * 8 + j]);
    }
}

// ---------------- head: out = sigmoid(h1 @ W2^T + b2) ----------------
__global__ void __launch_bounds__(256) final_kernel(const float* __restrict__ W2,
                                                    const float* __restrict__ b2,
                                                    float* __restrict__ out)
{
    int b = blockIdx.x, tid = threadIdx.x;
    const float* hp = g_h1 + (size_t)b * 2048;
    float s = 0.f;
    for (int k = tid; k < 2048; k += 256) s = fmaf(hp[k], W2[k], s);
    float dummy = 0.f;
    blockReduce2(s, dummy);
    if (tid == 0) out[b] = 1.f / (1.f + expf(-(s + b2[0])));
}

// ---------------- launch ----------------
extern "C" void kernel_launch(void* const* d_in, const int* in_sizes, int n_in,
                              void* d_out, int out_size)
{
    const int*   fen      = (const int*)  d_in[0];
    const int*   move     = (const int*)  d_in[1];
    const float* rank_emb = (const float*)d_in[2];
    const float* file_emb = (const float*)d_in[3];
    const float* fen_emb  = (const float*)d_in[4];
    const float* move_emb = (const float*)d_in[5];
    const float* ln_emb_g = (const float*)d_in[6];
    const float* ln_emb_b = (const float*)d_in[7];
    const float* abs_emb  = (const float*)d_in[8];
    const float* qkvw     = (const float*)d_in[9];
    const float* ff1w     = (const float*)d_in[10];
    const float* ff2w     = (const float*)d_in[11];
    const float* ln_out_g = (const float*)d_in[12];
    const float* ln_out_b = (const float*)d_in[13];
    const float* W1       = (const float*)d_in[14];
    const float* b1       = (const float*)d_in[15];
    const float* W2       = (const float*)d_in[16];
    const float* b2       = (const float*)d_in[17];
    float* out = (float*)d_out;

    const int ATTN_SMEM = (Tz * 128 * 2 + Tz * 129 + Tz * 72) * (int)sizeof(float); // 129788 B
    cudaFuncSetAttribute(attn_kernel, cudaFuncAttributeMaxDynamicSharedMemorySize, ATTN_SMEM);

    embed_kernel<<<NTOK, 256>>>(fen, move, rank_emb, file_emb, fen_emb, move_emb,
                                ln_emb_g, ln_emb_b, abs_emb);

    for (int l = 0; l < Lz; ++l) {
        qkv_kernel<<<dim3(MTILES, 24), 256>>>(qkvw + (size_t)l * 3 * Hz * DHz * DHz);
        attn_kernel<<<dim3(Bz, Hz), 256, ATTN_SMEM>>>();
        ff1_kernel<<<dim3(MTILES, Hz), 256>>>(ff1w + (size_t)l * Hz * Dz * DHz);
        ff2_kernel<<<dim3(MTILES, Hz), 256>>>(ff2w + (size_t)l * Hz * DHz * DHz);
    }

    transpose2048<<<dim3(64, 64), dim3(32, 8)>>>(W1);
    gather_ln_kernel<<<Bz, 256>>>(ln_out_g, ln_out_b);
    head_gemm_kernel<<<dim3(16, 16), 256>>>(b1);
    final_kernel<<<Bz, 256>>>(W2, b2, out);
}

// round 4
// speedup vs baseline: 1.2541x; 1.2541x over previous
#include <cuda_runtime.h>
#include <cuda_bf16.h>
#include <mma.h>
#include <math.h>
#include <stdint.h>

using namespace nvcuda;

// ---------------- problem constants ----------------
#define Bz   2048
#define Tz   71
#define Dz   1024
#define Hz   8
#define DHz  128
#define Lz   12
#define NTOK (Bz*Tz)            // 145408
#define MTILES (NTOK/128)       // 1136

// ---------------- device scratch ----------------
__device__ float g_x [NTOK*Dz];
__device__ float g_q [NTOK*Dz];
__device__ float g_k [NTOK*Dz];
__device__ float g_v [NTOK*Dz];
__device__ float g_y1[NTOK*Dz];
__device__ float g_t [Bz*2*Dz];
__device__ float g_h1[Bz*2*Dz];
__device__ float g_qkvT[Lz*3*Hz*DHz*DHz];   // [l][s][h][n][k]
__device__ float g_ff1T[Lz*Hz*DHz*Dz];      // [l][n(global 1024)][k=1024]
__device__ float g_ff2T[Lz*Hz*DHz*DHz];     // [l][h][n][k]

__device__ __forceinline__ float lrelu(float x) { return x > 0.f ? x : 0.2f * x; }

// ---------------- wmma tf32 GEMM core: CTA 128x128, 8 warps (4m x 2n) ----------------
using FragA = wmma::fragment<wmma::matrix_a, 16, 16, 8, wmma::precision::tf32, wmma::row_major>;
using FragB = wmma::fragment<wmma::matrix_b, 16, 16, 8, wmma::precision::tf32, wmma::col_major>;
using FragC = wmma::fragment<wmma::accumulator, 16, 16, 8, float>;

#define LDS 36   // smem row stride (floats), pad vs 32 to dodge bank conflicts

// A: row-major [128 x K] (lda), B: K-contiguous [128n x K] (ldb)  => C = A @ B^T
__device__ __forceinline__ void gemm_tile(const float* __restrict__ A, int lda,
                                          const float* __restrict__ B, int ldb,
                                          int K, FragC (&acc)[2][4],
                                          float* As, float* Bs)
{
    const int tid = threadIdx.x;
    const int warp = tid >> 5;
    const int wm = warp & 3;        // 0..3  (m offset = wm*32)
    const int wn = warp >> 2;       // 0..1  (n offset = wn*64)

#pragma unroll
    for (int i = 0; i < 2; ++i)
#pragma unroll
        for (int j = 0; j < 4; ++j)
            wmma::fill_fragment(acc[i][j], 0.f);

    for (int kk = 0; kk < K; kk += 32) {
#pragma unroll
        for (int it = 0; it < 4; ++it) {
            int idx = tid + it * 256;
            int row = idx >> 3, seg = idx & 7;
            float4 v = *reinterpret_cast<const float4*>(A + (size_t)row * lda + kk + seg * 4);
            float4 w = make_float4(wmma::__float_to_tf32(v.x), wmma::__float_to_tf32(v.y),
                                   wmma::__float_to_tf32(v.z), wmma::__float_to_tf32(v.w));
            *reinterpret_cast<float4*>(As + row * LDS + seg * 4) = w;
        }
#pragma unroll
        for (int it = 0; it < 4; ++it) {
            int idx = tid + it * 256;
            int row = idx >> 3, seg = idx & 7;
            float4 v = *reinterpret_cast<const float4*>(B + (size_t)row * ldb + kk + seg * 4);
            float4 w = make_float4(wmma::__float_to_tf32(v.x), wmma::__float_to_tf32(v.y),
                                   wmma::__float_to_tf32(v.z), wmma::__float_to_tf32(v.w));
            *reinterpret_cast<float4*>(Bs + row * LDS + seg * 4) = w;
        }
        __syncthreads();
#pragma unroll
        for (int ks = 0; ks < 4; ++ks) {
            FragA af[2];
            wmma::load_matrix_sync(af[0], As + (wm * 32) * LDS + ks * 8, LDS);
            wmma::load_matrix_sync(af[1], As + (wm * 32 + 16) * LDS + ks * 8, LDS);
#pragma unroll
            for (int j = 0; j < 4; ++j) {
                FragB bf;
                wmma::load_matrix_sync(bf, Bs + (wn * 64 + j * 16) * LDS + ks * 8, LDS);
                wmma::mma_sync(acc[0][j], af[0], bf, acc[0][j]);
                wmma::mma_sync(acc[1][j], af[1], bf, acc[1][j]);
            }
        }
        __syncthreads();
    }
}

// ---------------- GEMM kernels ----------------
// QKV: grid (24, MTILES): x = s*8+h (24 consecutive CTAs share A rows -> L2 reuse)
__global__ void __launch_bounds__(256) qkv_tc(const float* __restrict__ qkvT_l)
{
    __shared__ float As[128 * LDS];
    __shared__ float Bs[128 * LDS];
    int sh = blockIdx.x, s = sh >> 3, h = sh & 7;
    int m0 = blockIdx.y * 128;
    FragC acc[2][4];
    gemm_tile(g_x + (size_t)m0 * Dz + h * DHz, Dz,
              qkvT_l + (size_t)sh * (DHz * DHz), DHz, DHz, acc, As, Bs);

    float* out = (s == 0) ? g_q : (s == 1) ? g_k : g_v;
    int wm = (threadIdx.x >> 5) & 3, wn = threadIdx.x >> 7;
#pragma unroll
    for (int i = 0; i < 2; ++i)
#pragma unroll
        for (int j = 0; j < 4; ++j)
            wmma::store_matrix_sync(out + (size_t)(m0 + wm * 32 + i * 16) * Dz
                                        + h * DHz + wn * 64 + j * 16,
                                    acc[i][j], Dz, wmma::mem_row_major);
}

// FF1: grid (8, MTILES): x = n-tile; lrelu epilogue
__global__ void __launch_bounds__(256) ff1_tc(const float* __restrict__ ff1T_l)
{
    __shared__ float As[128 * LDS];
    __shared__ float Bs[128 * LDS];
    int n0 = blockIdx.x * 128, m0 = blockIdx.y * 128;
    FragC acc[2][4];
    gemm_tile(g_x + (size_t)m0 * Dz, Dz,
              ff1T_l + (size_t)n0 * Dz, Dz, Dz, acc, As, Bs);

    int wm = (threadIdx.x >> 5) & 3, wn = threadIdx.x >> 7;
#pragma unroll
    for (int i = 0; i < 2; ++i)
#pragma unroll
        for (int j = 0; j < 4; ++j) {
#pragma unroll
            for (int e = 0; e < acc[i][j].num_elements; ++e)
                acc[i][j].x[e] = lrelu(acc[i][j].x[e]);
            wmma::store_matrix_sync(g_y1 + (size_t)(m0 + wm * 32 + i * 16) * Dz
                                         + n0 + wn * 64 + j * 16,
                                    acc[i][j], Dz, wmma::mem_row_major);
        }
}

// FF2: grid (8, MTILES): x = h; lrelu + residual into g_x
__global__ void __launch_bounds__(256) ff2_tc(const float* __restrict__ ff2T_l)
{
    __shared__ float As[128 * LDS];
    __shared__ float Bs[128 * LDS];
    int h = blockIdx.x, m0 = blockIdx.y * 128;
    FragC acc[2][4];
    gemm_tile(g_y1 + (size_t)m0 * Dz + h * DHz, Dz,
              ff2T_l + (size_t)h * (DHz * DHz), DHz, DHz, acc, As, Bs);

    int wm = (threadIdx.x >> 5) & 3, wn = threadIdx.x >> 7;
#pragma unroll
    for (int i = 0; i < 2; ++i)
#pragma unroll
        for (int j = 0; j < 4; ++j) {
            float* dst = g_x + (size_t)(m0 + wm * 32 + i * 16) * Dz
                             + h * DHz + wn * 64 + j * 16;
            FragC c;
            wmma::load_matrix_sync(c, dst, Dz, wmma::mem_row_major);
#pragma unroll
            for (int e = 0; e < c.num_elements; ++e)
                c.x[e] += lrelu(acc[i][j].x[e]);
            wmma::store_matrix_sync(dst, c, Dz, wmma::mem_row_major);
        }
}

// HEAD: h1_raw = t @ W1^T ; grid (16, 16); bias+lrelu applied by head_bias kernel
__global__ void __launch_bounds__(256) head_tc(const float* __restrict__ W1)
{
    __shared__ float As[128 * LDS];
    __shared__ float Bs[128 * LDS];
    int n0 = blockIdx.x * 128, m0 = blockIdx.y * 128;
    FragC acc[2][4];
    gemm_tile(g_t + (size_t)m0 * 2048, 2048,
              W1 + (size_t)n0 * 2048, 2048, 2048, acc, As, Bs);

    int wm = (threadIdx.x >> 5) & 3, wn = threadIdx.x >> 7;
#pragma unroll
    for (int i = 0; i < 2; ++i)
#pragma unroll
        for (int j = 0; j < 4; ++j)
            wmma::store_matrix_sync(g_h1 + (size_t)(m0 + wm * 32 + i * 16) * 2048
                                         + n0 + wn * 64 + j * 16,
                                    acc[i][j], 2048, wmma::mem_row_major);
}

__global__ void __launch_bounds__(512) head_bias(const float* __restrict__ b1)
{
    int idx = blockIdx.x * 512 + threadIdx.x;
    g_h1[idx] = lrelu(g_h1[idx] + b1[idx & 2047]);
}

// ---------------- embedding + layernorm ----------------
__device__ __forceinline__ void blockReduce2(float& s1, float& s2) {
    __shared__ float buf[32];
    int lane = threadIdx.x & 31, warp = threadIdx.x >> 5;
#pragma unroll
    for (int o = 16; o; o >>= 1) {
        s1 += __shfl_xor_sync(0xffffffffu, s1, o);
        s2 += __shfl_xor_sync(0xffffffffu, s2, o);
    }
    if (lane == 0) { buf[warp] = s1; buf[16 + warp] = s2; }
    __syncthreads();
    float t1 = 0.f, t2 = 0.f;
#pragma unroll
    for (int w = 0; w < 8; ++w) { t1 += buf[w]; t2 += buf[16 + w]; }
    s1 = t1; s2 = t2;
}

__global__ void __launch_bounds__(256) embed_kernel(
    const int* __restrict__ fen, const int* __restrict__ move,
    const float* __restrict__ rank_emb, const float* __restrict__ file_emb,
    const float* __restrict__ fen_emb, const float* __restrict__ move_emb,
    const float* __restrict__ lng, const float* __restrict__ lnb,
    const float* __restrict__ abs_emb)
{
    int token = blockIdx.x;
    int b = token / Tz, t = token - b * Tz;
    int tid = threadIdx.x;
    float vals[4];

    if (t < 64) {
        int i1 = fen[b * 133 + t];
        int i2 = fen[b * 133 + 64 + t];
        int r = t >> 3, f = t & 7;
#pragma unroll
        for (int c = 0; c < 4; ++c) {
            int d = tid + c * 256;
            vals[c] = 0.5f * (fen_emb[i1 * Dz + d] + fen_emb[i2 * Dz + d]
                              + rank_emb[r * Dz + d] + file_emb[f * Dz + d])
                      + abs_emb[t * Dz + d];
        }
    } else if (t < 69) {
        int i1 = fen[b * 133 + 128 + (t - 64)];
#pragma unroll
        for (int c = 0; c < 4; ++c) {
            int d = tid + c * 256;
            vals[c] = fen_emb[i1 * Dz + d] + abs_emb[t * Dz + d];
        }
    } else {
        int i = t - 69;
        int m = move[b * 2 + i];
        int r = m >> 3, f = m & 7;
#pragma unroll
        for (int c = 0; c < 4; ++c) {
            int d = tid + c * 256;
            vals[c] = (rank_emb[r * Dz + d] + file_emb[f * Dz + d] + move_emb[i * Dz + d]) * 0.58f
                      + abs_emb[t * Dz + d];
        }
    }

    float s1 = 0.f, s2 = 0.f;
#pragma unroll
    for (int c = 0; c < 4; ++c) { s1 += vals[c]; s2 += vals[c] * vals[c]; }
    blockReduce2(s1, s2);
    float mean = s1 * (1.f / 1024.f);
    float var  = s2 * (1.f / 1024.f) - mean * mean;
    float inv  = rsqrtf(var + 1e-5f);

    float* xp = g_x + (size_t)token * Dz;
#pragma unroll
    for (int c = 0; c < 4; ++c) {
        int d = tid + c * 256;
        xp[d] = (vals[c] - mean) * inv * lng[d] + lnb[d];
    }
}

// ---------------- weight transpose: [K,128] -> [128,K] ----------------
__global__ void transposeW(const float* __restrict__ src, float* __restrict__ dst, int K)
{
    __shared__ float tile[32][33];
    size_t mstride = (size_t)K * 128;
    src += blockIdx.z * mstride;
    dst += blockIdx.z * mstride;
    int k0 = blockIdx.x * 32, n0 = blockIdx.y * 32;
    for (int i = threadIdx.y; i < 32; i += 8)
        tile[i][threadIdx.x] = src[(size_t)(k0 + i) * 128 + n0 + threadIdx.x];
    __syncthreads();
    for (int i = threadIdx.y; i < 32; i += 8)
        dst[(size_t)(n0 + i) * K + k0 + threadIdx.x] = tile[threadIdx.x][i];
}

// ---------------- attention (SIMT) ----------------
__global__ void __launch_bounds__(256) attn_kernel()
{
    int b = blockIdx.x, h = blockIdx.y;
    int tid = threadIdx.x;
    extern __shared__ float sm[];
    float* qs = sm;
    float* ks = qs + Tz * 128;
    float* vs = ks + Tz * 129;
    float* ps = vs + Tz * 128;

    const float* qb = g_q + ((size_t)b * Tz) * Dz + h * DHz;
    const float* kb = g_k + ((size_t)b * Tz) * Dz + h * DHz;
    const float* vb = g_v + ((size_t)b * Tz) * Dz + h * DHz;

    for (int i = tid; i < Tz * 128; i += 256) {
        int t = i >> 7, d = i & 127;
        qs[t * 128 + d] = qb[(size_t)t * Dz + d];
        ks[t * 129 + d] = kb[(size_t)t * Dz + d];
        vs[t * 128 + d] = vb[(size_t)t * Dz + d];
    }
    __syncthreads();

    const float inv_scale = 0.08838834764831845f;
    for (int idx = tid; idx < Tz * Tz; idx += 256) {
        int i = idx / Tz, j = idx - i * Tz;
        float s = 0.f;
#pragma unroll 8
        for (int dd = 0; dd < 128; ++dd)
            s = fmaf(qs[i * 128 + dd], ks[j * 129 + dd], s);
        ps[i * 72 + j] = s * inv_scale;
    }
    __syncthreads();

    int warp = tid >> 5, lane = tid & 31;
    for (int r = warp; r < Tz; r += 8) {
        float m = -1e30f;
        for (int j = lane; j < Tz; j += 32) m = fmaxf(m, ps[r * 72 + j]);
#pragma unroll
        for (int o = 16; o; o >>= 1) m = fmaxf(m, __shfl_xor_sync(0xffffffffu, m, o));
        float ssum = 0.f;
        for (int j = lane; j < Tz; j += 32) {
            float e = expf(ps[r * 72 + j] - m);
            ps[r * 72 + j] = e;
            ssum += e;
        }
#pragma unroll
        for (int o = 16; o; o >>= 1) ssum += __shfl_xor_sync(0xffffffffu, ssum, o);
        float inv = 1.f / ssum;
        for (int j = lane; j < Tz; j += 32) ps[r * 72 + j] *= inv;
    }
    __syncthreads();

    float* xb = g_x + ((size_t)b * Tz) * Dz + h * DHz;
    for (int idx = tid; idx < Tz * 128; idx += 256) {
        int i = idx >> 7, d = idx & 127;
        float a = 0.f;
#pragma unroll 8
        for (int j = 0; j < Tz; ++j)
            a = fmaf(ps[i * 72 + j], vs[j * 128 + d], a);
        xb[(size_t)i * Dz + d] += a;
    }
}

// ---------------- head: gather + LN over 2048 ----------------
__global__ void __launch_bounds__(256) gather_ln_kernel(const float* __restrict__ g,
                                                        const float* __restrict__ bb)
{
    int b = blockIdx.x, tid = threadIdx.x;
    const float* x69 = g_x + ((size_t)b * Tz + 69) * Dz;
    float vals[8];
#pragma unroll
    for (int c = 0; c < 8; ++c) vals[c] = x69[tid + c * 256];
    float s1 = 0.f, s2 = 0.f;
#pragma unroll
    for (int c = 0; c < 8; ++c) { s1 += vals[c]; s2 += vals[c] * vals[c]; }
    blockReduce2(s1, s2);
    float mean = s1 * (1.f / 2048.f);
    float var  = s2 * (1.f / 2048.f) - mean * mean;
    float inv  = rsqrtf(var + 1e-5f);
    float* tp = g_t + (size_t)b * 2048;
#pragma unroll
    for (int c = 0; c < 8; ++c) {
        int k = tid + c * 256;
        tp[k] = (vals[c] - mean) * inv * g[k] + bb[k];
    }
}

__global__ void __launch_bounds__(256) final_kernel(const float* __restrict__ W2,
                                                    const float* __restrict__ b2,
                                                    float* __restrict__ out)
{
    int b = blockIdx.x, tid = threadIdx.x;
    const float* hp = g_h1 + (size_t)b * 2048;
    float s = 0.f;
    for (int k = tid; k < 2048; k += 256) s = fmaf(hp[k], W2[k], s);
    float dummy = 0.f;
    blockReduce2(s, dummy);
    if (tid == 0) out[b] = 1.f / (1.f + expf(-(s + b2[0])));
}

// ---------------- launch ----------------
extern "C" void kernel_launch(void* const* d_in, const int* in_sizes, int n_in,
                              void* d_out, int out_size)
{
    const int*   fen      = (const int*)  d_in[0];
    const int*   move     = (const int*)  d_in[1];
    const float* rank_emb = (const float*)d_in[2];
    const float* file_emb = (const float*)d_in[3];
    const float* fen_emb  = (const float*)d_in[4];
    const float* move_emb = (const float*)d_in[5];
    const float* ln_emb_g = (const float*)d_in[6];
    const float* ln_emb_b = (const float*)d_in[7];
    const float* abs_emb  = (const float*)d_in[8];
    const float* qkvw     = (const float*)d_in[9];
    const float* ff1w     = (const float*)d_in[10];
    const float* ff2w     = (const float*)d_in[11];
    const float* ln_out_g = (const float*)d_in[12];
    const float* ln_out_b = (const float*)d_in[13];
    const float* W1       = (const float*)d_in[14];
    const float* b1       = (const float*)d_in[15];
    const float* W2       = (const float*)d_in[16];
    const float* b2       = (const float*)d_in[17];
    float* out = (float*)d_out;

    const int ATTN_SMEM = (Tz * 128 * 2 + Tz * 129 + Tz * 72) * (int)sizeof(float);
    cudaFuncSetAttribute(attn_kernel, cudaFuncAttributeMaxDynamicSharedMemorySize, ATTN_SMEM);

    // one-time weight transposes into K-contiguous layouts
    float* qkvT; cudaGetSymbolAddress((void**)&qkvT, g_qkvT);
    float* ff1T; cudaGetSymbolAddress((void**)&ff1T, g_ff1T);
    float* ff2T; cudaGetSymbolAddress((void**)&ff2T, g_ff2T);
    transposeW<<<dim3(4, 4, Lz * 3 * Hz), dim3(32, 8)>>>(qkvw, qkvT, 128);
    transposeW<<<dim3(32, 4, Lz * Hz), dim3(32, 8)>>>(ff1w, ff1T, 1024);
    transposeW<<<dim3(4, 4, Lz * Hz), dim3(32, 8)>>>(ff2w, ff2T, 128);

    embed_kernel<<<NTOK, 256>>>(fen, move, rank_emb, file_emb, fen_emb, move_emb,
                                ln_emb_g, ln_emb_b, abs_emb);

    for (int l = 0; l < Lz; ++l) {
        const float* qkvT_l = qkvT + (size_t)l * 3 * Hz * DHz * DHz;
        const float* ff1T_l = ff1T + (size_t)l * Hz * DHz * Dz;
        const float* ff2T_l = ff2T + (size_t)l * Hz * DHz * DHz;
        qkv_tc<<<dim3(24, MTILES), 256>>>(qkvT_l);
        attn_kernel<<<dim3(Bz, Hz), 256, ATTN_SMEM>>>();
        ff1_tc<<<dim3(8, MTILES), 256>>>(ff1T_l);
        ff2_tc<<<dim3(8, MTILES), 256>>>(ff2T_l);
    }

    gather_ln_kernel<<<Bz, 256>>>(ln_out_g, ln_out_b);
    head_tc<<<dim3(16, 16), 256>>>(W1);
    head_bias<<<(Bz * 2048) / 512, 512>>>(b1);
    final_kernel<<<Bz, 256>>>(W2, b2, out);
}